// round 1
// baseline (speedup 1.0000x reference)
#include <cuda_runtime.h>
#include <cuda_bf16.h>
#include <cstdint>

// Problem constants
#define M_DIM 4096
#define K_DIM 4096
#define N_DIM 11008
#define GRP   64

// GEMM tiling
#define BM 128
#define BN 128
#define BK 32
#define NTHREADS 256

// Scratch (device globals; no cudaMalloc allowed)
__device__ __nv_bfloat16 g_Xhi[(size_t)M_DIM * K_DIM];   // 32 MB
__device__ __nv_bfloat16 g_Xlo[(size_t)M_DIM * K_DIM];   // 32 MB
__device__ __nv_bfloat16 g_W[(size_t)N_DIM * K_DIM];     // 90 MB
__device__ float g_c[M_DIM];

// ---------------------------------------------------------------------------
// Helpers
// ---------------------------------------------------------------------------
__device__ __forceinline__ uint32_t smem_u32(const void* p) {
    return (uint32_t)__cvta_generic_to_shared(p);
}

__device__ __forceinline__ void cp16(uint32_t s, const void* g) {
    asm volatile("cp.async.cg.shared.global [%0], [%1], 16;\n" :: "r"(s), "l"(g));
}

__device__ __forceinline__ void cp_commit() {
    asm volatile("cp.async.commit_group;\n");
}

template <int N>
__device__ __forceinline__ void cp_wait() {
    asm volatile("cp.async.wait_group %0;\n" :: "n"(N));
}

__device__ __forceinline__ void ldsm4(uint32_t* r, uint32_t addr) {
    asm volatile("ldmatrix.sync.aligned.m8n8.x4.shared.b16 {%0,%1,%2,%3}, [%4];\n"
        : "=r"(r[0]), "=r"(r[1]), "=r"(r[2]), "=r"(r[3]) : "r"(addr));
}

__device__ __forceinline__ void mma16816(float* d, const uint32_t* a, uint32_t b0, uint32_t b1) {
    asm volatile(
        "mma.sync.aligned.m16n8k16.row.col.f32.bf16.bf16.f32 "
        "{%0,%1,%2,%3},{%4,%5,%6,%7},{%8,%9},{%0,%1,%2,%3};\n"
        : "+f"(d[0]), "+f"(d[1]), "+f"(d[2]), "+f"(d[3])
        : "r"(a[0]), "r"(a[1]), "r"(a[2]), "r"(a[3]), "r"(b0), "r"(b1));
}

// ---------------------------------------------------------------------------
// Prep kernel 1: X' = X * s[g], split into bf16 hi/lo; c[m] = sum_k X'[m,k]*zp[g]
// ---------------------------------------------------------------------------
__global__ void prep_x_kernel(const float* __restrict__ x,
                              const float* __restrict__ scales,
                              const float* __restrict__ zps) {
    int m = blockIdx.x;
    const float* xr = x + (size_t)m * K_DIM;
    size_t ob = (size_t)m * K_DIM;
    float csum = 0.f;
    for (int k = threadIdx.x; k < K_DIM; k += blockDim.x) {
        int gi = k >> 6;  // group index (GRP=64)
        float s = __ldg(scales + gi);
        float xp = xr[k] * s;
        __nv_bfloat16 h = __float2bfloat16(xp);
        float lo = xp - __bfloat162float(h);
        g_Xhi[ob + k] = h;
        g_Xlo[ob + k] = __float2bfloat16(lo);
        csum += xp * __ldg(zps + gi);
    }
    __shared__ float red[256];
    red[threadIdx.x] = csum;
    __syncthreads();
    for (int s = 128; s > 0; s >>= 1) {
        if (threadIdx.x < s) red[threadIdx.x] += red[threadIdx.x + s];
        __syncthreads();
    }
    if (threadIdx.x == 0) g_c[m] = red[0];
}

// ---------------------------------------------------------------------------
// Prep kernel 2: unpack int4 nibbles (low nibble = even k) to exact bf16
// ---------------------------------------------------------------------------
__global__ void prep_w_kernel(const int* __restrict__ pw) {
    size_t i = (size_t)blockIdx.x * blockDim.x + threadIdx.x;
    const size_t total = (size_t)N_DIM * (K_DIM / 2);
    if (i >= total) return;
    int v = pw[i];
    int lo = v & 15;
    int hi = (v >> 4) & 15;
    lo = (lo >= 8) ? lo - 16 : lo;
    hi = (hi >= 8) ? hi - 16 : hi;
    __nv_bfloat162 p;
    p.x = __float2bfloat16((float)lo);   // even k
    p.y = __float2bfloat16((float)hi);   // odd k
    reinterpret_cast<__nv_bfloat162*>(g_W)[i] = p;
}

// ---------------------------------------------------------------------------
// GEMM: out[m,n] = (Xhi+Xlo)[m,:] . W[n,:] - c[m] + bias[n]
// 128x128x32 block tile, 8 warps (2x4), warp tile 64x32, m16n8k16 bf16 mma,
// cp.async double buffering, XOR-swizzled smem for conflict-free ldmatrix.
// ---------------------------------------------------------------------------
__global__ void __launch_bounds__(NTHREADS, 1)
gemm_kernel(const float* __restrict__ bias, float* __restrict__ out) {
    extern __shared__ __align__(1024) char smem_raw[];
    const uint32_t sbase = smem_u32(smem_raw);
    // layout: Ahi[0],Ahi[1],Alo[0],Alo[1],B[0],B[1]; each tile 128*32*2 = 8192B
    const uint32_t sAhi0 = sbase;
    const uint32_t sAlo0 = sbase + 16384;
    const uint32_t sB0   = sbase + 32768;

    const int tid  = threadIdx.x;
    const int lane = tid & 31;
    const int warp = tid >> 5;
    const int wm = warp & 1;   // 0..1 along M (64 each)
    const int wn = warp >> 1;  // 0..3 along N (32 each)

    const int m0 = blockIdx.x * BM;
    const int n0 = blockIdx.y * BN;

    float acc[4][4][4];
#pragma unroll
    for (int i = 0; i < 4; i++)
#pragma unroll
        for (int j = 0; j < 4; j++)
#pragma unroll
            for (int v = 0; v < 4; v++) acc[i][j][v] = 0.f;

    const int NK = K_DIM / BK;  // 128

    // ---- stage loader: 512 chunks of 16B per tile, 2 per thread per tile ----
#define LOAD_STAGE(BUF, KT)                                                        \
    {                                                                              \
        _Pragma("unroll")                                                          \
        for (int i = 0; i < 2; i++) {                                              \
            int ch  = tid + i * 256;                                               \
            int row = ch >> 2;                                                     \
            int c   = ch & 3;                                                      \
            uint32_t soff = (uint32_t)(row * 64 + ((c ^ ((row >> 1) & 3)) << 4));  \
            size_t gk = (size_t)(KT) * BK + c * 8;                                 \
            cp16(sAhi0 + (BUF) * 8192 + soff,                                      \
                 g_Xhi + (size_t)(m0 + row) * K_DIM + gk);                         \
            cp16(sAlo0 + (BUF) * 8192 + soff,                                      \
                 g_Xlo + (size_t)(m0 + row) * K_DIM + gk);                         \
            cp16(sB0 + (BUF) * 8192 + soff,                                        \
                 g_W + (size_t)(n0 + row) * K_DIM + gk);                           \
        }                                                                          \
    }

    LOAD_STAGE(0, 0);
    cp_commit();
    LOAD_STAGE(1, 1);
    cp_commit();

    const int lrow  = lane & 15;       // row within a 16-row ldmatrix tile
    const int lcsel = lane >> 4;       // 0: k[0..7], 1: k[8..15]

    for (int kt = 0; kt < NK; kt++) {
        cp_wait<1>();
        __syncthreads();
        const int buf = kt & 1;
        const uint32_t aHi = sAhi0 + buf * 8192;
        const uint32_t aLo = sAlo0 + buf * 8192;
        const uint32_t bB  = sB0 + buf * 8192;

#pragma unroll
        for (int kk = 0; kk < 2; kk++) {
            const int ccol = kk * 2 + lcsel;  // 16B chunk within 64B row
            uint32_t ah[4][4], al[4][4], bb[2][4];
#pragma unroll
            for (int mt = 0; mt < 4; mt++) {
                int row = wm * 64 + mt * 16 + lrow;
                uint32_t soff = (uint32_t)(row * 64 + ((ccol ^ ((row >> 1) & 3)) << 4));
                ldsm4(ah[mt], aHi + soff);
                ldsm4(al[mt], aLo + soff);
            }
#pragma unroll
            for (int np = 0; np < 2; np++) {
                int row = wn * 32 + np * 16 + lrow;
                uint32_t soff = (uint32_t)(row * 64 + ((ccol ^ ((row >> 1) & 3)) << 4));
                ldsm4(bb[np], bB + soff);
            }
#pragma unroll
            for (int mt = 0; mt < 4; mt++) {
#pragma unroll
                for (int nt = 0; nt < 4; nt++) {
                    uint32_t b0 = bb[nt >> 1][nt & 1];
                    uint32_t b1 = bb[nt >> 1][2 + (nt & 1)];
                    mma16816(acc[mt][nt], ah[mt], b0, b1);
                    mma16816(acc[mt][nt], al[mt], b0, b1);
                }
            }
        }
        __syncthreads();
        if (kt + 2 < NK) LOAD_STAGE(buf, kt + 2);
        cp_commit();
    }

    // ---- epilogue: + bias[n] - c[m] ----
    const int g  = lane >> 2;
    const int tg = lane & 3;
#pragma unroll
    for (int mt = 0; mt < 4; mt++) {
        int row0 = m0 + wm * 64 + mt * 16 + g;
        int row1 = row0 + 8;
        float c0 = g_c[row0];
        float c1 = g_c[row1];
#pragma unroll
        for (int nt = 0; nt < 4; nt++) {
            int col = n0 + wn * 32 + nt * 8 + tg * 2;
            float2 bv = *reinterpret_cast<const float2*>(bias + col);
            float2 v0, v1;
            v0.x = acc[mt][nt][0] + bv.x - c0;
            v0.y = acc[mt][nt][1] + bv.y - c0;
            v1.x = acc[mt][nt][2] + bv.x - c1;
            v1.y = acc[mt][nt][3] + bv.y - c1;
            *reinterpret_cast<float2*>(out + (size_t)row0 * N_DIM + col) = v0;
            *reinterpret_cast<float2*>(out + (size_t)row1 * N_DIM + col) = v1;
        }
    }
#undef LOAD_STAGE
}

// ---------------------------------------------------------------------------
// Launch
// ---------------------------------------------------------------------------
extern "C" void kernel_launch(void* const* d_in, const int* in_sizes, int n_in,
                              void* d_out, int out_size) {
    const float* x    = (const float*)d_in[0];
    const int*   pw   = (const int*)d_in[1];
    const float* sc   = (const float*)d_in[2];
    const float* zp   = (const float*)d_in[3];
    const float* bias = (const float*)d_in[4];
    float* out = (float*)d_out;

    prep_x_kernel<<<M_DIM, 256>>>(x, sc, zp);

    const size_t wtotal = (size_t)N_DIM * (K_DIM / 2);
    prep_w_kernel<<<(unsigned)((wtotal + 255) / 256), 256>>>(pw);

    dim3 grid(M_DIM / BM, N_DIM / BN);  // (32, 86); x=m fastest keeps A hot in L2
    gemm_kernel<<<grid, NTHREADS, 49152>>>(bias, out);
}

// round 3
// speedup vs baseline: 1.6282x; 1.6282x over previous
#include <cuda_runtime.h>
#include <cuda_fp16.h>
#include <cstdint>

// Problem constants
#define M_DIM 4096
#define K_DIM 4096
#define N_DIM 11008

// GEMM tiling
#define BM 128
#define BN 256
#define BK 32
#define NTHREADS 512

#define A_STAGE_BYTES (BM * 64)                      // 8192  (128 rows x 64B)
#define B_STAGE_BYTES (BN * 64)                      // 16384 (256 rows x 64B)
#define STAGE_BYTES   (A_STAGE_BYTES + B_STAGE_BYTES) // 24576
#define SMEM_TOTAL    (2 * STAGE_BYTES)               // 49152

// Scratch (device globals; no cudaMalloc allowed)
__device__ __half g_X[(size_t)M_DIM * K_DIM];   // 32 MB  (x * scale, fp16)
__device__ __half g_W[(size_t)N_DIM * K_DIM];   // 90 MB  (exact int4 values)
__device__ float  g_c[M_DIM];

// ---------------------------------------------------------------------------
// Helpers
// ---------------------------------------------------------------------------
__device__ __forceinline__ uint32_t smem_u32(const void* p) {
    return (uint32_t)__cvta_generic_to_shared(p);
}
__device__ __forceinline__ void cp16(uint32_t s, const void* g) {
    asm volatile("cp.async.cg.shared.global [%0], [%1], 16;\n" :: "r"(s), "l"(g));
}
__device__ __forceinline__ void cp_commit() {
    asm volatile("cp.async.commit_group;\n");
}
template <int N>
__device__ __forceinline__ void cp_wait() {
    asm volatile("cp.async.wait_group %0;\n" :: "n"(N));
}
__device__ __forceinline__ void ldsm4(uint32_t* r, uint32_t addr) {
    asm volatile("ldmatrix.sync.aligned.m8n8.x4.shared.b16 {%0,%1,%2,%3}, [%4];\n"
        : "=r"(r[0]), "=r"(r[1]), "=r"(r[2]), "=r"(r[3]) : "r"(addr));
}
__device__ __forceinline__ void mma16816(float* d, const uint32_t* a, uint32_t b0, uint32_t b1) {
    asm volatile(
        "mma.sync.aligned.m16n8k16.row.col.f32.f16.f16.f32 "
        "{%0,%1,%2,%3},{%4,%5,%6,%7},{%8,%9},{%0,%1,%2,%3};\n"
        : "+f"(d[0]), "+f"(d[1]), "+f"(d[2]), "+f"(d[3])
        : "r"(a[0]), "r"(a[1]), "r"(a[2]), "r"(a[3]), "r"(b0), "r"(b1));
}

// ---------------------------------------------------------------------------
// Prep kernel 1: X' = X * s[g] in fp16; c[m] = sum_k X'[m,k]*zp[g]  (fp32)
// ---------------------------------------------------------------------------
__global__ void prep_x_kernel(const float* __restrict__ x,
                              const float* __restrict__ scales,
                              const float* __restrict__ zps) {
    int m = blockIdx.x;
    const float* xr = x + (size_t)m * K_DIM;
    size_t ob = (size_t)m * K_DIM;
    float csum = 0.f;
    for (int k = threadIdx.x; k < K_DIM; k += blockDim.x) {
        int gi = k >> 6;  // group index (G=64)
        float s = __ldg(scales + gi);
        float xp = xr[k] * s;
        g_X[ob + k] = __float2half(xp);
        csum += xp * __ldg(zps + gi);
    }
    __shared__ float red[256];
    red[threadIdx.x] = csum;
    __syncthreads();
    for (int s = 128; s > 0; s >>= 1) {
        if (threadIdx.x < s) red[threadIdx.x] += red[threadIdx.x + s];
        __syncthreads();
    }
    if (threadIdx.x == 0) g_c[m] = red[0];
}

// ---------------------------------------------------------------------------
// Prep kernel 2: unpack int4 nibbles (low nibble = even k) to exact fp16
// ---------------------------------------------------------------------------
__global__ void prep_w_kernel(const int* __restrict__ pw) {
    size_t i = (size_t)blockIdx.x * blockDim.x + threadIdx.x;
    const size_t total = (size_t)N_DIM * (K_DIM / 2);
    if (i >= total) return;
    int v = pw[i];
    int lo = v & 15;
    int hi = (v >> 4) & 15;
    lo = (lo >= 8) ? lo - 16 : lo;
    hi = (hi >= 8) ? hi - 16 : hi;
    __half2 p;
    p.x = __float2half((float)lo);   // even k
    p.y = __float2half((float)hi);   // odd k
    reinterpret_cast<__half2*>(g_W)[i] = p;
}

// ---------------------------------------------------------------------------
// GEMM: out[m,n] = X'[m,:] . W[n,:] - c[m] + bias[n]
// 128x256x32 block tile, 16 warps (2x8), warp tile 64x32, m16n8k16 fp16 mma,
// cp.async double buffering, XOR-swizzled smem for conflict-free ldmatrix.
// ---------------------------------------------------------------------------
__global__ void __launch_bounds__(NTHREADS, 1)
gemm_kernel(const float* __restrict__ bias, float* __restrict__ out) {
    extern __shared__ __align__(1024) char smem_raw[];
    const uint32_t sbase = smem_u32(smem_raw);
    // layout per stage: A (8192B) then B (16384B); two stages
    const uint32_t sA0 = sbase;
    const uint32_t sB0 = sbase + A_STAGE_BYTES;

    const int tid  = threadIdx.x;
    const int lane = tid & 31;
    const int warp = tid >> 5;
    const int wm = warp & 1;   // 0..1 along M (64 rows each)
    const int wn = warp >> 1;  // 0..7 along N (32 cols each)

    const int m0 = blockIdx.x * BM;
    const int n0 = blockIdx.y * BN;

    float acc[4][4][4];
#pragma unroll
    for (int i = 0; i < 4; i++)
#pragma unroll
        for (int j = 0; j < 4; j++)
#pragma unroll
            for (int v = 0; v < 4; v++) acc[i][j][v] = 0.f;

    const int NK = K_DIM / BK;  // 128

    // stage loader: A 512 chunks (1/thread), B 1024 chunks (2/thread), 16B each
#define LOAD_STAGE(BUF, KT)                                                        \
    {                                                                              \
        uint32_t _a = sA0 + (BUF) * STAGE_BYTES;                                   \
        uint32_t _b = sB0 + (BUF) * STAGE_BYTES;                                   \
        size_t _gk = (size_t)(KT) * BK;                                            \
        {                                                                          \
            int row = tid >> 2, c = tid & 3;                                       \
            uint32_t soff = (uint32_t)(row * 64 + ((c ^ ((row >> 1) & 3)) << 4));  \
            cp16(_a + soff, g_X + (size_t)(m0 + row) * K_DIM + _gk + c * 8);       \
        }                                                                          \
        _Pragma("unroll")                                                          \
        for (int i = 0; i < 2; i++) {                                              \
            int j = tid + i * 512;                                                 \
            int row = j >> 2, c = j & 3;                                           \
            uint32_t soff = (uint32_t)(row * 64 + ((c ^ ((row >> 1) & 3)) << 4));  \
            cp16(_b + soff, g_W + (size_t)(n0 + row) * K_DIM + _gk + c * 8);       \
        }                                                                          \
    }

    LOAD_STAGE(0, 0);
    cp_commit();
    LOAD_STAGE(1, 1);
    cp_commit();

    const int lrow  = lane & 15;       // row within a 16-row ldmatrix tile
    const int lcsel = lane >> 4;       // 0: k[0..7], 1: k[8..15]

    for (int kt = 0; kt < NK; kt++) {
        cp_wait<1>();
        __syncthreads();
        const int buf = kt & 1;
        const uint32_t aT = sA0 + buf * STAGE_BYTES;
        const uint32_t bT = sB0 + buf * STAGE_BYTES;

#pragma unroll
        for (int kk = 0; kk < 2; kk++) {
            const int ccol = kk * 2 + lcsel;  // 16B chunk within 64B row
            uint32_t ah[4][4], bb[2][4];
#pragma unroll
            for (int mt = 0; mt < 4; mt++) {
                int row = wm * 64 + mt * 16 + lrow;
                uint32_t soff = (uint32_t)(row * 64 + ((ccol ^ ((row >> 1) & 3)) << 4));
                ldsm4(ah[mt], aT + soff);
            }
#pragma unroll
            for (int np = 0; np < 2; np++) {
                int row = wn * 32 + np * 16 + lrow;
                uint32_t soff = (uint32_t)(row * 64 + ((ccol ^ ((row >> 1) & 3)) << 4));
                ldsm4(bb[np], bT + soff);
            }
#pragma unroll
            for (int mt = 0; mt < 4; mt++) {
#pragma unroll
                for (int nt = 0; nt < 4; nt++) {
                    uint32_t b0 = bb[nt >> 1][nt & 1];
                    uint32_t b1 = bb[nt >> 1][2 + (nt & 1)];
                    mma16816(acc[mt][nt], ah[mt], b0, b1);
                }
            }
        }
        __syncthreads();
        if (kt + 2 < NK) LOAD_STAGE(buf, kt + 2);
        cp_commit();
    }

    // ---- epilogue: + bias[n] - c[m] ----
    const int g  = lane >> 2;
    const int tg = lane & 3;
#pragma unroll
    for (int mt = 0; mt < 4; mt++) {
        int row0 = m0 + wm * 64 + mt * 16 + g;
        int row1 = row0 + 8;
        float c0 = g_c[row0];
        float c1 = g_c[row1];
#pragma unroll
        for (int nt = 0; nt < 4; nt++) {
            int col = n0 + wn * 32 + nt * 8 + tg * 2;
            float2 bv = *reinterpret_cast<const float2*>(bias + col);
            float2 v0, v1;
            v0.x = acc[mt][nt][0] + bv.x - c0;
            v0.y = acc[mt][nt][1] + bv.y - c0;
            v1.x = acc[mt][nt][2] + bv.x - c1;
            v1.y = acc[mt][nt][3] + bv.y - c1;
            *reinterpret_cast<float2*>(out + (size_t)row0 * N_DIM + col) = v0;
            *reinterpret_cast<float2*>(out + (size_t)row1 * N_DIM + col) = v1;
        }
    }
#undef LOAD_STAGE
}

// ---------------------------------------------------------------------------
// Launch
// ---------------------------------------------------------------------------
extern "C" void kernel_launch(void* const* d_in, const int* in_sizes, int n_in,
                              void* d_out, int out_size) {
    const float* x    = (const float*)d_in[0];
    const int*   pw   = (const int*)d_in[1];
    const float* sc   = (const float*)d_in[2];
    const float* zp   = (const float*)d_in[3];
    const float* bias = (const float*)d_in[4];
    float* out = (float*)d_out;

    prep_x_kernel<<<M_DIM, 256>>>(x, sc, zp);

    const size_t wtotal = (size_t)N_DIM * (K_DIM / 2);
    prep_w_kernel<<<(unsigned)((wtotal + 255) / 256), 256>>>(pw);

    dim3 grid(M_DIM / BM, N_DIM / BN);  // (32, 43); x=m fastest keeps A hot in L2
    gemm_kernel<<<grid, NTHREADS, SMEM_TOTAL>>>(bias, out);
}

// round 4
// speedup vs baseline: 1.6600x; 1.0195x over previous
#include <cuda_runtime.h>
#include <cuda_fp16.h>
#include <cstdint>

// Problem constants
#define M_DIM 4096
#define K_DIM 4096
#define N_DIM 11008

// GEMM tiling
#define BM 128
#define BN 256
#define BK 32
#define NTHREADS 256          // 8 warps, warp tile 64x64 (2 x 4)
#define NSTAGE 3

#define A_STAGE_BYTES (BM * 64)                        // 8192
#define B_STAGE_BYTES (BN * 64)                        // 16384
#define STAGE_BYTES   (A_STAGE_BYTES + B_STAGE_BYTES)  // 24576
#define SMEM_TOTAL    (NSTAGE * STAGE_BYTES)           // 73728

// Scratch (device globals; no cudaMalloc allowed)
__device__ __half g_X[(size_t)M_DIM * K_DIM];   // 32 MB  (x * scale, fp16)
__device__ __half g_W[(size_t)N_DIM * K_DIM];   // 90 MB  (exact int4 values)
__device__ float  g_c[M_DIM];

// ---------------------------------------------------------------------------
// Helpers
// ---------------------------------------------------------------------------
__device__ __forceinline__ uint32_t smem_u32(const void* p) {
    return (uint32_t)__cvta_generic_to_shared(p);
}
__device__ __forceinline__ void cp16(uint32_t s, const void* g) {
    asm volatile("cp.async.cg.shared.global [%0], [%1], 16;\n" :: "r"(s), "l"(g));
}
__device__ __forceinline__ void cp_commit() {
    asm volatile("cp.async.commit_group;\n");
}
template <int N>
__device__ __forceinline__ void cp_wait() {
    asm volatile("cp.async.wait_group %0;\n" :: "n"(N));
}
__device__ __forceinline__ void ldsm4(uint32_t* r, uint32_t addr) {
    asm volatile("ldmatrix.sync.aligned.m8n8.x4.shared.b16 {%0,%1,%2,%3}, [%4];\n"
        : "=r"(r[0]), "=r"(r[1]), "=r"(r[2]), "=r"(r[3]) : "r"(addr));
}
__device__ __forceinline__ void mma16816(float* d, const uint32_t* a, uint32_t b0, uint32_t b1) {
    asm volatile(
        "mma.sync.aligned.m16n8k16.row.col.f32.f16.f16.f32 "
        "{%0,%1,%2,%3},{%4,%5,%6,%7},{%8,%9},{%0,%1,%2,%3};\n"
        : "+f"(d[0]), "+f"(d[1]), "+f"(d[2]), "+f"(d[3])
        : "r"(a[0]), "r"(a[1]), "r"(a[2]), "r"(a[3]), "r"(b0), "r"(b1));
}

// ---------------------------------------------------------------------------
// Prep kernel 1: X' = X * s[g] in fp16; c[m] = sum_k X'[m,k]*zp[g]  (fp32)
// ---------------------------------------------------------------------------
__global__ void prep_x_kernel(const float* __restrict__ x,
                              const float* __restrict__ scales,
                              const float* __restrict__ zps) {
    int m = blockIdx.x;
    const float* xr = x + (size_t)m * K_DIM;
    size_t ob = (size_t)m * K_DIM;
    float csum = 0.f;
    for (int k = threadIdx.x; k < K_DIM; k += blockDim.x) {
        int gi = k >> 6;  // group index (G=64)
        float s = __ldg(scales + gi);
        float xp = xr[k] * s;
        g_X[ob + k] = __float2half(xp);
        csum += xp * __ldg(zps + gi);
    }
    __shared__ float red[256];
    red[threadIdx.x] = csum;
    __syncthreads();
    for (int s = 128; s > 0; s >>= 1) {
        if (threadIdx.x < s) red[threadIdx.x] += red[threadIdx.x + s];
        __syncthreads();
    }
    if (threadIdx.x == 0) g_c[m] = red[0];
}

// ---------------------------------------------------------------------------
// Prep kernel 2: unpack int4 nibbles (low nibble = even k) to exact fp16
// ---------------------------------------------------------------------------
__global__ void prep_w_kernel(const int* __restrict__ pw) {
    size_t i = (size_t)blockIdx.x * blockDim.x + threadIdx.x;
    const size_t total = (size_t)N_DIM * (K_DIM / 2);
    if (i >= total) return;
    int v = pw[i];
    int lo = v & 15;
    int hi = (v >> 4) & 15;
    lo = (lo >= 8) ? lo - 16 : lo;
    hi = (hi >= 8) ? hi - 16 : hi;
    __half2 p;
    p.x = __float2half((float)lo);   // even k
    p.y = __float2half((float)hi);   // odd k
    reinterpret_cast<__half2*>(g_W)[i] = p;
}

// ---------------------------------------------------------------------------
// GEMM: out[m,n] = X'[m,:] . W[n,:] - c[m] + bias[n]
// 128x256x32 block tile, 8 warps (2x4), warp tile 64x64, m16n8k16 fp16 mma,
// 3-stage cp.async pipeline, single barrier per k-tile, XOR-swizzled smem.
// ---------------------------------------------------------------------------
__global__ void __launch_bounds__(NTHREADS, 1)
gemm_kernel(const float* __restrict__ bias, float* __restrict__ out) {
    extern __shared__ __align__(1024) char smem_raw[];
    const uint32_t sbase = smem_u32(smem_raw);

    const int tid  = threadIdx.x;
    const int lane = tid & 31;
    const int warp = tid >> 5;
    const int wm = warp & 1;   // 0..1 along M (64 rows each)
    const int wn = warp >> 1;  // 0..3 along N (64 cols each)

    const int m0 = blockIdx.x * BM;
    const int n0 = blockIdx.y * BN;

    float acc[4][8][4];
#pragma unroll
    for (int i = 0; i < 4; i++)
#pragma unroll
        for (int j = 0; j < 8; j++)
#pragma unroll
            for (int v = 0; v < 4; v++) acc[i][j][v] = 0.f;

    const int NK = K_DIM / BK;  // 128

    // stage loader: A 512 chunks (2/thread), B 1024 chunks (4/thread), 16B each
#define LOAD_STAGE(S, KT)                                                          \
    {                                                                              \
        uint32_t _a = sbase + (S) * STAGE_BYTES;                                   \
        uint32_t _b = _a + A_STAGE_BYTES;                                          \
        size_t _gk = (size_t)(KT) * BK;                                            \
        _Pragma("unroll")                                                          \
        for (int i = 0; i < 2; i++) {                                              \
            int j = tid + i * 256;                                                 \
            int row = j >> 2, c = j & 3;                                           \
            uint32_t soff = (uint32_t)(row * 64 + ((c ^ ((row >> 1) & 3)) << 4));  \
            cp16(_a + soff, g_X + (size_t)(m0 + row) * K_DIM + _gk + c * 8);       \
        }                                                                          \
        _Pragma("unroll")                                                          \
        for (int i = 0; i < 4; i++) {                                              \
            int j = tid + i * 256;                                                 \
            int row = j >> 2, c = j & 3;                                           \
            uint32_t soff = (uint32_t)(row * 64 + ((c ^ ((row >> 1) & 3)) << 4));  \
            cp16(_b + soff, g_W + (size_t)(n0 + row) * K_DIM + _gk + c * 8);       \
        }                                                                          \
    }

    LOAD_STAGE(0, 0);
    cp_commit();
    LOAD_STAGE(1, 1);
    cp_commit();

    const int lrow  = lane & 15;       // row within a 16-row ldmatrix tile
    const int lcsel = lane >> 4;       // 0: k[0..7], 1: k[8..15]

    for (int kt = 0; kt < NK; kt++) {
        // stage kt complete for this thread; barrier publishes it to all warps
        // and simultaneously frees stage (kt-1)%3 for overwrite.
        cp_wait<1>();
        __syncthreads();
        if (kt + 2 < NK) LOAD_STAGE((kt + 2) % NSTAGE, kt + 2);
        cp_commit();   // one group per iteration keeps wait counts aligned

        const uint32_t aT = sbase + (kt % NSTAGE) * STAGE_BYTES;
        const uint32_t bT = aT + A_STAGE_BYTES;

#pragma unroll
        for (int kk = 0; kk < 2; kk++) {
            const int ccol = kk * 2 + lcsel;  // 16B chunk within 64B row
            uint32_t ah[4][4], bb[4][4];
#pragma unroll
            for (int mt = 0; mt < 4; mt++) {
                int row = wm * 64 + mt * 16 + lrow;
                uint32_t soff = (uint32_t)(row * 64 + ((ccol ^ ((row >> 1) & 3)) << 4));
                ldsm4(ah[mt], aT + soff);
            }
#pragma unroll
            for (int np = 0; np < 4; np++) {
                int row = wn * 64 + np * 16 + lrow;
                uint32_t soff = (uint32_t)(row * 64 + ((ccol ^ ((row >> 1) & 3)) << 4));
                ldsm4(bb[np], bT + soff);
            }
#pragma unroll
            for (int mt = 0; mt < 4; mt++) {
#pragma unroll
                for (int nt = 0; nt < 8; nt++) {
                    uint32_t b0 = bb[nt >> 1][nt & 1];
                    uint32_t b1 = bb[nt >> 1][2 + (nt & 1)];
                    mma16816(acc[mt][nt], ah[mt], b0, b1);
                }
            }
        }
    }

    // ---- epilogue: + bias[n] - c[m] ----
    const int g  = lane >> 2;
    const int tg = lane & 3;
#pragma unroll
    for (int mt = 0; mt < 4; mt++) {
        int row0 = m0 + wm * 64 + mt * 16 + g;
        int row1 = row0 + 8;
        float c0 = g_c[row0];
        float c1 = g_c[row1];
#pragma unroll
        for (int nt = 0; nt < 8; nt++) {
            int col = n0 + wn * 64 + nt * 8 + tg * 2;
            float2 bv = *reinterpret_cast<const float2*>(bias + col);
            float2 v0, v1;
            v0.x = acc[mt][nt][0] + bv.x - c0;
            v0.y = acc[mt][nt][1] + bv.y - c0;
            v1.x = acc[mt][nt][2] + bv.x - c1;
            v1.y = acc[mt][nt][3] + bv.y - c1;
            *reinterpret_cast<float2*>(out + (size_t)row0 * N_DIM + col) = v0;
            *reinterpret_cast<float2*>(out + (size_t)row1 * N_DIM + col) = v1;
        }
    }
#undef LOAD_STAGE
}

// ---------------------------------------------------------------------------
// Launch
// ---------------------------------------------------------------------------
extern "C" void kernel_launch(void* const* d_in, const int* in_sizes, int n_in,
                              void* d_out, int out_size) {
    const float* x    = (const float*)d_in[0];
    const int*   pw   = (const int*)d_in[1];
    const float* sc   = (const float*)d_in[2];
    const float* zp   = (const float*)d_in[3];
    const float* bias = (const float*)d_in[4];
    float* out = (float*)d_out;

    prep_x_kernel<<<M_DIM, 256>>>(x, sc, zp);

    const size_t wtotal = (size_t)N_DIM * (K_DIM / 2);
    prep_w_kernel<<<(unsigned)((wtotal + 255) / 256), 256>>>(pw);

    cudaFuncSetAttribute(gemm_kernel,
                         cudaFuncAttributeMaxDynamicSharedMemorySize, SMEM_TOTAL);
    dim3 grid(M_DIM / BM, N_DIM / BN);  // (32, 43); x=m fastest keeps B shared in L2
    gemm_kernel<<<grid, NTHREADS, SMEM_TOTAL>>>(bias, out);
}